// round 1
// baseline (speedup 1.0000x reference)
#include <cuda_runtime.h>

// ---------------------------------------------------------------------------
// Scratch (device globals — no allocation allowed)
// ---------------------------------------------------------------------------
__device__ float g_q [8388608];   // [4*2048, 1024]  = 32MB
__device__ float g_kv[16777216];  // [4*2048, 2048]  = 64MB (k | v)
__device__ float g_o [8388608];   // [4*2048, 1024]  = 32MB

// ---------------------------------------------------------------------------
// Fast exp2 on the FMA pipe (avoids MUFU throughput wall).
// Valid for x <= 0 (softmax domain). Rel err ~2.4e-6.
// ---------------------------------------------------------------------------
__device__ __forceinline__ float fast_exp2(float x) {
    x = fmaxf(x, -126.0f);
    float xr = x + 12582912.0f;               // 1.5 * 2^23 : round-to-nearest
    float fl = xr - 12582912.0f;              // round(x)
    float f  = x - fl;                        // f in [-0.5, 0.5]
    int   e  = __float_as_int(xr) - 0x4B400000;
    float p  = 1.3333558e-3f;
    p = fmaf(p, f, 9.6181291e-3f);
    p = fmaf(p, f, 5.5504109e-2f);
    p = fmaf(p, f, 2.4022651e-1f);
    p = fmaf(p, f, 6.9314718e-1f);
    p = fmaf(p, f, 1.0f);
    return p * __int_as_float((e + 127) << 23);
}

// ---------------------------------------------------------------------------
// Tiled fp32 GEMM: C[M,N] = A[M,K] @ B[K,N] (+ bias[N]).
// BM=BN=128, BK=16, 256 threads, 8x8 per thread (split 4+4 columns).
// M % 128 == 0, N % 128 == 0, K % 16 == 0 (true for all three calls).
// ---------------------------------------------------------------------------
__global__ void __launch_bounds__(256) gemm128(const float* __restrict__ A,
                                               const float* __restrict__ B,
                                               float* __restrict__ C,
                                               int M, int N, int K,
                                               const float* __restrict__ bias)
{
    __shared__ float As[16][128];
    __shared__ float Bs[16][128];

    const int t  = threadIdx.x;
    const int tx = t & 15;           // 0..15
    const int ty = t >> 4;           // 0..15
    const int bx = blockIdx.x, by = blockIdx.y;

    const float* Ab = A + (size_t)by * 128 * K;
    const float* Bb = B + (size_t)bx * 128;

    float4 acc[8][2];
#pragma unroll
    for (int i = 0; i < 8; i++) {
        acc[i][0] = make_float4(0.f, 0.f, 0.f, 0.f);
        acc[i][1] = make_float4(0.f, 0.f, 0.f, 0.f);
    }

    const int row0 = ty * 8;
    const int c0   = tx * 4;
    const int c1   = 64 + tx * 4;

    for (int k0 = 0; k0 < K; k0 += 16) {
        // A tile 128x16 -> As[c][r] (transposed in smem)
#pragma unroll
        for (int j = 0; j < 2; j++) {
            int idx4 = j * 256 + t;          // 0..511 float4s
            int r    = idx4 >> 2;            // 0..127
            int cc   = (idx4 & 3) << 2;      // 0,4,8,12
            float4 av = *(const float4*)(Ab + (size_t)r * K + k0 + cc);
            As[cc + 0][r] = av.x;
            As[cc + 1][r] = av.y;
            As[cc + 2][r] = av.z;
            As[cc + 3][r] = av.w;
        }
        // B tile 16x128 -> Bs[c][n]
#pragma unroll
        for (int j = 0; j < 2; j++) {
            int idx4 = j * 256 + t;
            int c    = idx4 >> 5;            // 0..15
            int n4   = (idx4 & 31) << 2;     // 0..124
            *(float4*)(&Bs[c][n4]) = *(const float4*)(Bb + (size_t)(k0 + c) * N + n4);
        }
        __syncthreads();

#pragma unroll
        for (int kk = 0; kk < 16; kk++) {
            float4 a0 = *(const float4*)(&As[kk][row0]);
            float4 a1 = *(const float4*)(&As[kk][row0 + 4]);
            float4 b0 = *(const float4*)(&Bs[kk][c0]);
            float4 b1 = *(const float4*)(&Bs[kk][c1]);
            float av[8] = {a0.x, a0.y, a0.z, a0.w, a1.x, a1.y, a1.z, a1.w};
#pragma unroll
            for (int i = 0; i < 8; i++) {
                acc[i][0].x = fmaf(av[i], b0.x, acc[i][0].x);
                acc[i][0].y = fmaf(av[i], b0.y, acc[i][0].y);
                acc[i][0].z = fmaf(av[i], b0.z, acc[i][0].z);
                acc[i][0].w = fmaf(av[i], b0.w, acc[i][0].w);
                acc[i][1].x = fmaf(av[i], b1.x, acc[i][1].x);
                acc[i][1].y = fmaf(av[i], b1.y, acc[i][1].y);
                acc[i][1].z = fmaf(av[i], b1.z, acc[i][1].z);
                acc[i][1].w = fmaf(av[i], b1.w, acc[i][1].w);
            }
        }
        __syncthreads();
    }

    float4 bias0 = make_float4(0.f, 0.f, 0.f, 0.f);
    float4 bias1 = bias0;
    if (bias) {
        bias0 = *(const float4*)(bias + bx * 128 + c0);
        bias1 = *(const float4*)(bias + bx * 128 + c1);
    }
#pragma unroll
    for (int i = 0; i < 8; i++) {
        size_t row = (size_t)by * 128 + row0 + i;
        float4 r0 = acc[i][0];
        r0.x += bias0.x; r0.y += bias0.y; r0.z += bias0.z; r0.w += bias0.w;
        float4 r1 = acc[i][1];
        r1.x += bias1.x; r1.y += bias1.y; r1.z += bias1.z; r1.w += bias1.w;
        *(float4*)(C + row * N + bx * 128 + c0) = r0;
        *(float4*)(C + row * N + bx * 128 + c1) = r1;
    }
}

// ---------------------------------------------------------------------------
// Causal flash attention, fp32. One thread per query row.
// BR = 64 rows/block, 64 threads. Q row + O accumulator in registers.
// K/V tiles in smem (broadcast reads -> conflict-free, no padding).
// S staged transposed in smem (s_s[j][t] -> lane-contiguous, conflict-free).
// Static smem = 3 * 16KB = 48KB exactly.
// Q is pre-scaled by SCALE * log2(e) so softmax runs in exp2 domain.
// ---------------------------------------------------------------------------
__global__ void __launch_bounds__(64) attn64(const float* __restrict__ Q,
                                             const float* __restrict__ KV,
                                             float* __restrict__ O)
{
    __shared__ float k_s[4096];   // [64][64]
    __shared__ float v_s[4096];   // [64][64]
    __shared__ float s_s[4096];   // [64 j][64 t]  (transposed)

    const int t  = threadIdx.x;                         // query row in tile
    const int qt = (int)gridDim.x - 1 - (int)blockIdx.x; // heavy tiles first
    const int h  = blockIdx.y;
    const int b  = blockIdx.z;
    const int i  = qt * 64 + t;                         // global query row (in batch)

    const size_t kvbase = ((size_t)b * 2048) * 2048 + (size_t)h * 64;
    const float  scale  = 0.125f * 1.4426950408889634f; // D^-0.5 * log2(e)

    // Q row -> registers (scaled)
    float4 qr[16];
    const float* qrow = Q + ((size_t)b * 2048 + i) * 1024 + h * 64;
#pragma unroll
    for (int d4 = 0; d4 < 16; d4++) {
        float4 qv = *(const float4*)(qrow + d4 * 4);
        qr[d4].x = qv.x * scale; qr[d4].y = qv.y * scale;
        qr[d4].z = qv.z * scale; qr[d4].w = qv.w * scale;
    }

    float m = -1e30f, l = 0.f;
    float4 o4[16];
#pragma unroll
    for (int d4 = 0; d4 < 16; d4++) o4[d4] = make_float4(0.f, 0.f, 0.f, 0.f);

    const int ntiles = qt + 1;  // causal: key tiles 0..qt
    for (int kt = 0; kt < ntiles; kt++) {
        const int kb = kt * 64;
        __syncthreads();   // previous tile's k_s/v_s reads complete
        for (int idx = t; idx < 1024; idx += 64) {
            int r = idx >> 4, d4 = (idx & 15) << 2;
            const float* src = KV + kvbase + (size_t)(kb + r) * 2048 + d4;
            *(float4*)(k_s + r * 64 + d4) = *(const float4*)(src);
            *(float4*)(v_s + r * 64 + d4) = *(const float4*)(src + 1024);
        }
        __syncthreads();

        // S row: s[j] = q . k_j  (k broadcast across lanes)
        float tmax = -1e30f;
        for (int j = 0; j < 64; j++) {
            float4 a = make_float4(0.f, 0.f, 0.f, 0.f);
            const float* kr = k_s + j * 64;
#pragma unroll
            for (int d4 = 0; d4 < 16; d4++) {
                float4 kv4 = *(const float4*)(kr + d4 * 4);
                a.x = fmaf(qr[d4].x, kv4.x, a.x);
                a.y = fmaf(qr[d4].y, kv4.y, a.y);
                a.z = fmaf(qr[d4].z, kv4.z, a.z);
                a.w = fmaf(qr[d4].w, kv4.w, a.w);
            }
            float sj = (a.x + a.y) + (a.z + a.w);
            if (kb + j > i) sj = -1e30f;    // causal mask
            tmax = fmaxf(tmax, sj);
            s_s[j * 64 + t] = sj;
        }

        // Online softmax rescale
        float m_new = fmaxf(m, tmax);
        float alpha = fast_exp2(m - m_new);
        l *= alpha;
#pragma unroll
        for (int d4 = 0; d4 < 16; d4++) {
            o4[d4].x *= alpha; o4[d4].y *= alpha;
            o4[d4].z *= alpha; o4[d4].w *= alpha;
        }

        // P . V accumulate (v broadcast across lanes)
        for (int j = 0; j < 64; j++) {
            float p = fast_exp2(s_s[j * 64 + t] - m_new);
            l += p;
            const float* vr = v_s + j * 64;
#pragma unroll
            for (int d4 = 0; d4 < 16; d4++) {
                float4 vv = *(const float4*)(vr + d4 * 4);
                o4[d4].x = fmaf(p, vv.x, o4[d4].x);
                o4[d4].y = fmaf(p, vv.y, o4[d4].y);
                o4[d4].z = fmaf(p, vv.z, o4[d4].z);
                o4[d4].w = fmaf(p, vv.w, o4[d4].w);
            }
        }
        m = m_new;
    }

    const float inv = 1.0f / l;
    float* orow = O + ((size_t)b * 2048 + i) * 1024 + h * 64;
#pragma unroll
    for (int d4 = 0; d4 < 16; d4++) {
        float4 ov = o4[d4];
        ov.x *= inv; ov.y *= inv; ov.z *= inv; ov.w *= inv;
        *(float4*)(orow + d4 * 4) = ov;
    }
}

// ---------------------------------------------------------------------------
// Launch: q = x@Wq ; kv = x@Wkv ; attn ; out = o@Wo + bo
// ---------------------------------------------------------------------------
extern "C" void kernel_launch(void* const* d_in, const int* in_sizes, int n_in,
                              void* d_out, int out_size)
{
    (void)in_sizes; (void)n_in; (void)out_size;
    const float* x   = (const float*)d_in[0];   // [4,2048,1024]
    const float* Wq  = (const float*)d_in[1];   // [1024,1024]
    const float* Wkv = (const float*)d_in[2];   // [1024,2048]
    const float* Wo  = (const float*)d_in[3];   // [1024,1024]
    const float* bo  = (const float*)d_in[4];   // [1024]
    float* out = (float*)d_out;                 // [4,2048,1024]

    float *qb, *kvb, *ob;
    cudaGetSymbolAddress((void**)&qb,  g_q);
    cudaGetSymbolAddress((void**)&kvb, g_kv);
    cudaGetSymbolAddress((void**)&ob,  g_o);

    const int M = 8192, K = 1024;

    gemm128<<<dim3(8,  64), 256>>>(x,  Wq,  qb,  M, 1024, K, nullptr);
    gemm128<<<dim3(16, 64), 256>>>(x,  Wkv, kvb, M, 2048, K, nullptr);
    attn64 <<<dim3(32, 16, 4), 64>>>(qb, kvb, ob);
    gemm128<<<dim3(8,  64), 256>>>(ob, Wo,  out, M, 1024, K, bo);
}

// round 3
// speedup vs baseline: 1.3617x; 1.3617x over previous
#include <cuda_runtime.h>
#include <cuda_bf16.h>
#include <cstdint>

// ---------------------------------------------------------------------------
// Scratch (device globals — no allocation allowed)
// ---------------------------------------------------------------------------
__device__ float g_q [8388608];            // [8192,1024] fp32 (gemm1 out)
__device__ float g_kv[16777216];           // [8192,2048] fp32 (gemm2 out)
__device__ __nv_bfloat16 g_xhi[8388608];   // x split hi
__device__ __nv_bfloat16 g_xlo[8388608];   // x split lo
__device__ __nv_bfloat16 g_wthi[4194304];  // Wq^T(1M) | Wkv^T(2M) | Wo^T(1M)
__device__ __nv_bfloat16 g_wtlo[4194304];
__device__ __nv_bfloat16 g_ohi[8388608];   // attn out split hi
__device__ __nv_bfloat16 g_olo[8388608];   // attn out split lo

// ---------------------------------------------------------------------------
// PTX helpers (baseline sm_80+ instructions only: HMMA/ldmatrix/cp.async)
// ---------------------------------------------------------------------------
__device__ __forceinline__ uint32_t smem_u32(const void* p) {
    uint32_t a;
    asm("{ .reg .u64 t; cvta.to.shared.u64 t, %1; cvt.u32.u64 %0, t; }" : "=r"(a) : "l"(p));
    return a;
}
#define CP_ASYNC16(dst, src) \
    asm volatile("cp.async.cg.shared.global [%0], [%1], 16;" :: "r"(dst), "l"(src) : "memory")
#define CP_COMMIT()  asm volatile("cp.async.commit_group;" ::: "memory")
#define CP_WAIT1()   asm volatile("cp.async.wait_group 1;" ::: "memory")
#define CP_WAIT0()   asm volatile("cp.async.wait_group 0;" ::: "memory")

__device__ __forceinline__ void ldsm4(uint32_t* r, uint32_t addr) {
    asm volatile("ldmatrix.sync.aligned.m8n8.x4.shared.b16 {%0,%1,%2,%3}, [%4];"
                 : "=r"(r[0]), "=r"(r[1]), "=r"(r[2]), "=r"(r[3]) : "r"(addr));
}
__device__ __forceinline__ void mma16816(float* c, const uint32_t* a, uint32_t b0, uint32_t b1) {
    asm volatile(
        "mma.sync.aligned.m16n8k16.row.col.f32.bf16.bf16.f32 "
        "{%0,%1,%2,%3}, {%4,%5,%6,%7}, {%8,%9}, {%0,%1,%2,%3};"
        : "+f"(c[0]), "+f"(c[1]), "+f"(c[2]), "+f"(c[3])
        : "r"(a[0]), "r"(a[1]), "r"(a[2]), "r"(a[3]), "r"(b0), "r"(b1));
}

// ---------------------------------------------------------------------------
// Prep: fp32 -> bf16 hi/lo split (x and attention output path)
// ---------------------------------------------------------------------------
__global__ void __launch_bounds__(256) conv_split(const float* __restrict__ in,
                                                  __nv_bfloat16* __restrict__ hi,
                                                  __nv_bfloat16* __restrict__ lo)
{
    size_t i4 = (size_t)blockIdx.x * 256 + threadIdx.x;
    float4 v = ((const float4*)in)[i4];
    __nv_bfloat16 h0 = __float2bfloat16_rn(v.x), h1 = __float2bfloat16_rn(v.y);
    __nv_bfloat16 h2 = __float2bfloat16_rn(v.z), h3 = __float2bfloat16_rn(v.w);
    __nv_bfloat16 l0 = __float2bfloat16_rn(v.x - __bfloat162float(h0));
    __nv_bfloat16 l1 = __float2bfloat16_rn(v.y - __bfloat162float(h1));
    __nv_bfloat16 l2 = __float2bfloat16_rn(v.z - __bfloat162float(h2));
    __nv_bfloat16 l3 = __float2bfloat16_rn(v.w - __bfloat162float(h3));
    __nv_bfloat162 hp0(h0, h1), hp1(h2, h3), lp0(l0, l1), lp1(l2, l3);
    uint2 hv, lv;
    hv.x = *(uint32_t*)&hp0; hv.y = *(uint32_t*)&hp1;
    lv.x = *(uint32_t*)&lp0; lv.y = *(uint32_t*)&lp1;
    ((uint2*)hi)[i4] = hv;
    ((uint2*)lo)[i4] = lv;
}

// Transpose + split weights: W[K=1024][N] -> Wt_hi/lo[N][1024]
__global__ void __launch_bounds__(256) conv_wT(const float* __restrict__ W,
                                               __nv_bfloat16* __restrict__ Thi,
                                               __nv_bfloat16* __restrict__ Tlo,
                                               int N)
{
    __shared__ float s[32][33];
    const int tx = threadIdx.x, ty = threadIdx.y;       // 32 x 8
    const int kt = blockIdx.y * 32, nt = blockIdx.x * 32;
#pragma unroll
    for (int r = 0; r < 4; r++) {
        int k = ty + r * 8;
        s[k][tx] = W[(size_t)(kt + k) * N + nt + tx];
    }
    __syncthreads();
#pragma unroll
    for (int r = 0; r < 4; r++) {
        int n = ty + r * 8;
        float v = s[tx][n];
        __nv_bfloat16 h = __float2bfloat16_rn(v);
        __nv_bfloat16 l = __float2bfloat16_rn(v - __bfloat162float(h));
        size_t o = (size_t)(nt + n) * 1024 + kt + tx;
        Thi[o] = h; Tlo[o] = l;
    }
}

// ---------------------------------------------------------------------------
// HMMA split-bf16 GEMM: C[M,N] = A[M,1024] @ B[1024,N] (+bias)
// A given as hi/lo bf16 [M][1024]; B given transposed hi/lo bf16 [N][1024].
// Tile 128x128, K-chunk 64, 256 thr (8 warps, warp tile 32x64), double-buffered
// cp.async. Rows padded to 144B (72 elems) -> conflict-free ldmatrix.
// ---------------------------------------------------------------------------
#define TILE_B   18432          // 128 rows * 144 B
#define BUF_B    (4 * TILE_B)   // Ahi | Alo | Bhi | Blo
#define GEMM_SMEM (2 * BUF_B)   // 147456

__global__ void __launch_bounds__(256) gemm_hmma(const __nv_bfloat16* __restrict__ Ahi,
                                                 const __nv_bfloat16* __restrict__ Alo,
                                                 const __nv_bfloat16* __restrict__ Bhi,
                                                 const __nv_bfloat16* __restrict__ Blo,
                                                 float* __restrict__ C,
                                                 int N,
                                                 const float* __restrict__ bias)
{
    extern __shared__ char smem[];
    const uint32_t sbase = smem_u32(smem);
    const int t    = threadIdx.x;
    const int lane = t & 31;
    const int wid  = t >> 5;
    const int bm   = blockIdx.y * 128;
    const int bn   = blockIdx.x * 128;
    const int wm   = (wid >> 1) * 32;   // warp m-offset
    const int wn   = (wid & 1) * 64;    // warp n-offset

    // ldmatrix per-lane byte offsets within a [128][72] bf16 tile (144B rows)
    const uint32_t a_off = (uint32_t)(wm + (lane & 15)) * 144 + (uint32_t)(lane >> 4) * 16;
    const uint32_t b_off = (uint32_t)(wn + ((lane >> 4) & 1) * 8 + (lane & 7)) * 144
                         + (uint32_t)((lane >> 3) & 1) * 16;

    const __nv_bfloat16* srcs[4] = { Ahi + (size_t)bm * 1024, Alo + (size_t)bm * 1024,
                                     Bhi + (size_t)bn * 1024, Blo + (size_t)bn * 1024 };

    // issue cp.async for iteration 'it' into buffer (it&1)
    auto issue = [&](int it) {
        const uint32_t bufb = sbase + (it & 1) * BUF_B;
        const int k0 = it * 64;
#pragma unroll
        for (int r = 0; r < 4; r++) {
            const __nv_bfloat16* gb = srcs[r] + k0;
            const uint32_t sb = bufb + r * TILE_B;
#pragma unroll
            for (int i = 0; i < 4; i++) {
                int c   = i * 256 + t;       // 0..1023
                int row = c >> 3;
                int col = c & 7;             // 16B chunk
                CP_ASYNC16(sb + row * 144 + col * 16,
                           gb + (size_t)row * 1024 + col * 8);
            }
        }
        CP_COMMIT();
    };

    float c[2][8][4];
#pragma unroll
    for (int mi = 0; mi < 2; mi++)
#pragma unroll
        for (int nj = 0; nj < 8; nj++)
#pragma unroll
            for (int k = 0; k < 4; k++) c[mi][nj][k] = 0.f;

    issue(0);
    issue(1);

    const int NITER = 16;   // K = 1024, chunk 64
    for (int it = 0; it < NITER; it++) {
        if (it + 1 < NITER) { CP_WAIT1(); } else { CP_WAIT0(); }
        __syncthreads();

        const uint32_t bufb = sbase + (it & 1) * BUF_B;
        const uint32_t Ah = bufb, Al = bufb + TILE_B, Bh = bufb + 2 * TILE_B, Bl = bufb + 3 * TILE_B;

#pragma unroll
        for (int ks = 0; ks < 4; ks++) {
            const uint32_t ko = ks * 32;   // 16 k-elems = 32 bytes
            uint32_t ah0[4], ah1[4], al0[4], al1[4];
            ldsm4(ah0, Ah + a_off + ko);
            ldsm4(ah1, Ah + a_off + 16 * 144 + ko);
            ldsm4(al0, Al + a_off + ko);
            ldsm4(al1, Al + a_off + 16 * 144 + ko);
            uint32_t bh[4][4], bl[4][4];
#pragma unroll
            for (int jj = 0; jj < 4; jj++) {
                ldsm4(bh[jj], Bh + b_off + jj * 16 * 144 + ko);
                ldsm4(bl[jj], Bl + b_off + jj * 16 * 144 + ko);
            }
#pragma unroll
            for (int nj = 0; nj < 8; nj++) {
                const uint32_t bh0 = bh[nj >> 1][(nj & 1) * 2], bh1 = bh[nj >> 1][(nj & 1) * 2 + 1];
                const uint32_t bl0 = bl[nj >> 1][(nj & 1) * 2], bl1 = bl[nj >> 1][(nj & 1) * 2 + 1];
                mma16816(c[0][nj], ah0, bh0, bh1);
                mma16816(c[1][nj], ah1, bh0, bh1);
                mma16816(c[0][nj], al0, bh0, bh1);
                mma16816(c[1][nj], al1, bh0, bh1);
                mma16816(c[0][nj], ah0, bl0, bl1);
                mma16816(c[1][nj], ah1, bl0, bl1);
            }
        }
        __syncthreads();
        if (it + 2 < NITER) issue(it + 2);
    }

    // epilogue: c0/c1 -> row g, cols 2tg..; c2/c3 -> row g+8
    const int g = lane >> 2, tg = lane & 3;
#pragma unroll
    for (int mi = 0; mi < 2; mi++) {
#pragma unroll
        for (int nj = 0; nj < 8; nj++) {
            int row = bm + wm + 16 * mi + g;
            int col = bn + wn + 8 * nj + 2 * tg;
            float b0 = 0.f, b1 = 0.f;
            if (bias) { b0 = bias[col]; b1 = bias[col + 1]; }
            float2 v0 = make_float2(c[mi][nj][0] + b0, c[mi][nj][1] + b1);
            float2 v1 = make_float2(c[mi][nj][2] + b0, c[mi][nj][3] + b1);
            *(float2*)(C + (size_t)row * N + col)       = v0;
            *(float2*)(C + (size_t)(row + 8) * N + col) = v1;
        }
    }
}

// ---------------------------------------------------------------------------
// Fast exp2 on the FMA pipe. Valid for x <= 0. Rel err ~2.4e-6.
// ---------------------------------------------------------------------------
__device__ __forceinline__ float fast_exp2(float x) {
    x = fmaxf(x, -126.0f);
    float xr = x + 12582912.0f;
    float fl = xr - 12582912.0f;
    float f  = x - fl;
    int   e  = __float_as_int(xr) - 0x4B400000;
    float p  = 1.3333558e-3f;
    p = fmaf(p, f, 9.6181291e-3f);
    p = fmaf(p, f, 5.5504109e-2f);
    p = fmaf(p, f, 2.4022651e-1f);
    p = fmaf(p, f, 6.9314718e-1f);
    p = fmaf(p, f, 1.0f);
    return p * __int_as_float((e + 127) << 23);
}

// ---------------------------------------------------------------------------
// Causal flash attention, fp32 math; epilogue emits hi/lo bf16 split for gemm3.
// ---------------------------------------------------------------------------
__global__ void __launch_bounds__(64) attn64(const float* __restrict__ Q,
                                             const float* __restrict__ KV,
                                             __nv_bfloat16* __restrict__ Ohi,
                                             __nv_bfloat16* __restrict__ Olo)
{
    __shared__ float k_s[4096];
    __shared__ float v_s[4096];
    __shared__ float s_s[4096];

    const int t  = threadIdx.x;
    const int qt = (int)gridDim.x - 1 - (int)blockIdx.x;
    const int h  = blockIdx.y;
    const int b  = blockIdx.z;
    const int i  = qt * 64 + t;

    const size_t kvbase = ((size_t)b * 2048) * 2048 + (size_t)h * 64;
    const float  scale  = 0.125f * 1.4426950408889634f;

    float4 qr[16];
    const float* qrow = Q + ((size_t)b * 2048 + i) * 1024 + h * 64;
#pragma unroll
    for (int d4 = 0; d4 < 16; d4++) {
        float4 qv = *(const float4*)(qrow + d4 * 4);
        qr[d4].x = qv.x * scale; qr[d4].y = qv.y * scale;
        qr[d4].z = qv.z * scale; qr[d4].w = qv.w * scale;
    }

    float m = -1e30f, l = 0.f;
    float4 o4[16];
#pragma unroll
    for (int d4 = 0; d4 < 16; d4++) o4[d4] = make_float4(0.f, 0.f, 0.f, 0.f);

    const int ntiles = qt + 1;
    for (int kt = 0; kt < ntiles; kt++) {
        const int kb = kt * 64;
        __syncthreads();
        for (int idx = t; idx < 1024; idx += 64) {
            int r = idx >> 4, d4 = (idx & 15) << 2;
            const float* src = KV + kvbase + (size_t)(kb + r) * 2048 + d4;
            *(float4*)(k_s + r * 64 + d4) = *(const float4*)(src);
            *(float4*)(v_s + r * 64 + d4) = *(const float4*)(src + 1024);
        }
        __syncthreads();

        float tmax = -1e30f;
        for (int j = 0; j < 64; j++) {
            float4 a = make_float4(0.f, 0.f, 0.f, 0.f);
            const float* kr = k_s + j * 64;
#pragma unroll
            for (int d4 = 0; d4 < 16; d4++) {
                float4 kv4 = *(const float4*)(kr + d4 * 4);
                a.x = fmaf(qr[d4].x, kv4.x, a.x);
                a.y = fmaf(qr[d4].y, kv4.y, a.y);
                a.z = fmaf(qr[d4].z, kv4.z, a.z);
                a.w = fmaf(qr[d4].w, kv4.w, a.w);
            }
            float sj = (a.x + a.y) + (a.z + a.w);
            if (kb + j > i) sj = -1e30f;
            tmax = fmaxf(tmax, sj);
            s_s[j * 64 + t] = sj;
        }

        float m_new = fmaxf(m, tmax);
        float alpha = fast_exp2(m - m_new);
        l *= alpha;
#pragma unroll
        for (int d4 = 0; d4 < 16; d4++) {
            o4[d4].x *= alpha; o4[d4].y *= alpha;
            o4[d4].z *= alpha; o4[d4].w *= alpha;
        }

        for (int j = 0; j < 64; j++) {
            float p = fast_exp2(s_s[j * 64 + t] - m_new);
            l += p;
            const float* vr = v_s + j * 64;
#pragma unroll
            for (int d4 = 0; d4 < 16; d4++) {
                float4 vv = *(const float4*)(vr + d4 * 4);
                o4[d4].x = fmaf(p, vv.x, o4[d4].x);
                o4[d4].y = fmaf(p, vv.y, o4[d4].y);
                o4[d4].z = fmaf(p, vv.z, o4[d4].z);
                o4[d4].w = fmaf(p, vv.w, o4[d4].w);
            }
        }
        m = m_new;
    }

    const float inv = 1.0f / l;
    const size_t obase = ((size_t)b * 2048 + i) * 1024 + h * 64;
#pragma unroll
    for (int d4 = 0; d4 < 16; d4++) {
        float vx = o4[d4].x * inv, vy = o4[d4].y * inv;
        float vz = o4[d4].z * inv, vw = o4[d4].w * inv;
        __nv_bfloat16 h0 = __float2bfloat16_rn(vx), h1 = __float2bfloat16_rn(vy);
        __nv_bfloat16 h2 = __float2bfloat16_rn(vz), h3 = __float2bfloat16_rn(vw);
        __nv_bfloat16 l0 = __float2bfloat16_rn(vx - __bfloat162float(h0));
        __nv_bfloat16 l1 = __float2bfloat16_rn(vy - __bfloat162float(h1));
        __nv_bfloat16 l2 = __float2bfloat16_rn(vz - __bfloat162float(h2));
        __nv_bfloat16 l3 = __float2bfloat16_rn(vw - __bfloat162float(h3));
        __nv_bfloat162 hp0(h0, h1), hp1(h2, h3), lp0(l0, l1), lp1(l2, l3);
        uint2 hv, lv;
        hv.x = *(uint32_t*)&hp0; hv.y = *(uint32_t*)&hp1;
        lv.x = *(uint32_t*)&lp0; lv.y = *(uint32_t*)&lp1;
        *(uint2*)(Ohi + obase + d4 * 4) = hv;
        *(uint2*)(Olo + obase + d4 * 4) = lv;
    }
}

// ---------------------------------------------------------------------------
// Launch
// ---------------------------------------------------------------------------
extern "C" void kernel_launch(void* const* d_in, const int* in_sizes, int n_in,
                              void* d_out, int out_size)
{
    (void)in_sizes; (void)n_in; (void)out_size;
    const float* x   = (const float*)d_in[0];
    const float* Wq  = (const float*)d_in[1];
    const float* Wkv = (const float*)d_in[2];
    const float* Wo  = (const float*)d_in[3];
    const float* bo  = (const float*)d_in[4];
    float* out = (float*)d_out;

    float *qb, *kvb;
    __nv_bfloat16 *xhi, *xlo, *wthi, *wtlo, *ohi, *olo;
    cudaGetSymbolAddress((void**)&qb,   g_q);
    cudaGetSymbolAddress((void**)&kvb,  g_kv);
    cudaGetSymbolAddress((void**)&xhi,  g_xhi);
    cudaGetSymbolAddress((void**)&xlo,  g_xlo);
    cudaGetSymbolAddress((void**)&wthi, g_wthi);
    cudaGetSymbolAddress((void**)&wtlo, g_wtlo);
    cudaGetSymbolAddress((void**)&ohi,  g_ohi);
    cudaGetSymbolAddress((void**)&olo,  g_olo);

    cudaFuncSetAttribute(gemm_hmma, cudaFuncAttributeMaxDynamicSharedMemorySize, GEMM_SMEM);

    // weight layout in scratch: Wq^T [0,1M) | Wkv^T [1M,3M) | Wo^T [3M,4M)
    __nv_bfloat16 *wq_hi = wthi,           *wq_lo = wtlo;
    __nv_bfloat16 *wkv_hi = wthi + 1048576, *wkv_lo = wtlo + 1048576;
    __nv_bfloat16 *wo_hi = wthi + 3145728, *wo_lo = wtlo + 3145728;

    // prep
    conv_split<<<8192, 256>>>(x, xhi, xlo);
    conv_wT<<<dim3(32, 32), dim3(32, 8)>>>(Wq,  wq_hi,  wq_lo,  1024);
    conv_wT<<<dim3(64, 32), dim3(32, 8)>>>(Wkv, wkv_hi, wkv_lo, 2048);
    conv_wT<<<dim3(32, 32), dim3(32, 8)>>>(Wo,  wo_hi,  wo_lo,  1024);

    // q = x @ Wq ; kv = x @ Wkv
    gemm_hmma<<<dim3(8,  64), 256, GEMM_SMEM>>>(xhi, xlo, wq_hi,  wq_lo,  qb,  1024, nullptr);
    gemm_hmma<<<dim3(16, 64), 256, GEMM_SMEM>>>(xhi, xlo, wkv_hi, wkv_lo, kvb, 2048, nullptr);

    // attention (fp32), emits bf16 hi/lo output
    attn64<<<dim3(32, 16, 4), 64>>>(qb, kvb, ohi, olo);

    // out = o @ Wo + bo
    gemm_hmma<<<dim3(8, 64), 256, GEMM_SMEM>>>(ohi, olo, wo_hi, wo_lo, out, 1024, bo);
}

// round 4
// speedup vs baseline: 2.8740x; 2.1106x over previous
#include <cuda_runtime.h>
#include <cuda_bf16.h>
#include <cstdint>

// ---------------------------------------------------------------------------
// Scratch (device globals — no allocation allowed)
// ---------------------------------------------------------------------------
__device__ __nv_bfloat16 g_xhi[8388608];   // x split hi
__device__ __nv_bfloat16 g_xlo[8388608];
__device__ __nv_bfloat16 g_wthi[4194304];  // Wq^T(1M) | Wkv^T(2M) | Wo^T(1M)
__device__ __nv_bfloat16 g_wtlo[4194304];
__device__ __nv_bfloat16 g_qhi[8388608];   // q (scaled) hi/lo
__device__ __nv_bfloat16 g_qlo[8388608];
__device__ __nv_bfloat16 g_kvhi[16777216]; // kv hi/lo
__device__ __nv_bfloat16 g_kvlo[16777216];
__device__ __nv_bfloat16 g_ohi[8388608];   // attn out hi/lo
__device__ __nv_bfloat16 g_olo[8388608];

// ---------------------------------------------------------------------------
// PTX helpers (baseline sm_80+: HMMA / ldmatrix / cp.async)
// ---------------------------------------------------------------------------
__device__ __forceinline__ uint32_t smem_u32(const void* p) {
    uint32_t a;
    asm("{ .reg .u64 t; cvta.to.shared.u64 t, %1; cvt.u32.u64 %0, t; }" : "=r"(a) : "l"(p));
    return a;
}
#define CP_ASYNC16(dst, src) \
    asm volatile("cp.async.cg.shared.global [%0], [%1], 16;" :: "r"(dst), "l"(src) : "memory")
#define CP_COMMIT()  asm volatile("cp.async.commit_group;" ::: "memory")
#define CP_WAIT1()   asm volatile("cp.async.wait_group 1;" ::: "memory")
#define CP_WAIT0()   asm volatile("cp.async.wait_group 0;" ::: "memory")

__device__ __forceinline__ void ldsm4(uint32_t* r, uint32_t addr) {
    asm volatile("ldmatrix.sync.aligned.m8n8.x4.shared.b16 {%0,%1,%2,%3}, [%4];"
                 : "=r"(r[0]), "=r"(r[1]), "=r"(r[2]), "=r"(r[3]) : "r"(addr));
}
__device__ __forceinline__ void ldsm4t(uint32_t* r, uint32_t addr) {
    asm volatile("ldmatrix.sync.aligned.m8n8.x4.trans.shared.b16 {%0,%1,%2,%3}, [%4];"
                 : "=r"(r[0]), "=r"(r[1]), "=r"(r[2]), "=r"(r[3]) : "r"(addr));
}
__device__ __forceinline__ void mma16816(float* c, const uint32_t* a, uint32_t b0, uint32_t b1) {
    asm volatile(
        "mma.sync.aligned.m16n8k16.row.col.f32.bf16.bf16.f32 "
        "{%0,%1,%2,%3}, {%4,%5,%6,%7}, {%8,%9}, {%0,%1,%2,%3};"
        : "+f"(c[0]), "+f"(c[1]), "+f"(c[2]), "+f"(c[3])
        : "r"(a[0]), "r"(a[1]), "r"(a[2]), "r"(a[3]), "r"(b0), "r"(b1));
}
__device__ __forceinline__ uint32_t pack_bf16(float x, float y) {
    __nv_bfloat162 p(__float2bfloat16_rn(x), __float2bfloat16_rn(y));
    return *(uint32_t*)&p;
}

// ---------------------------------------------------------------------------
// Fast exp2 on the FMA pipe. Valid for x <= 0. Rel err ~2.4e-6.
// ---------------------------------------------------------------------------
__device__ __forceinline__ float fast_exp2(float x) {
    x = fmaxf(x, -126.0f);
    float xr = x + 12582912.0f;
    float fl = xr - 12582912.0f;
    float f  = x - fl;
    int   e  = __float_as_int(xr) - 0x4B400000;
    float p  = 1.3333558e-3f;
    p = fmaf(p, f, 9.6181291e-3f);
    p = fmaf(p, f, 5.5504109e-2f);
    p = fmaf(p, f, 2.4022651e-1f);
    p = fmaf(p, f, 6.9314718e-1f);
    p = fmaf(p, f, 1.0f);
    return p * __int_as_float((e + 127) << 23);
}

// ---------------------------------------------------------------------------
// Prep kernels
// ---------------------------------------------------------------------------
__global__ void __launch_bounds__(256) conv_split(const float* __restrict__ in,
                                                  __nv_bfloat16* __restrict__ hi,
                                                  __nv_bfloat16* __restrict__ lo)
{
    size_t i4 = (size_t)blockIdx.x * 256 + threadIdx.x;
    float4 v = ((const float4*)in)[i4];
    __nv_bfloat16 h0 = __float2bfloat16_rn(v.x), h1 = __float2bfloat16_rn(v.y);
    __nv_bfloat16 h2 = __float2bfloat16_rn(v.z), h3 = __float2bfloat16_rn(v.w);
    __nv_bfloat16 l0 = __float2bfloat16_rn(v.x - __bfloat162float(h0));
    __nv_bfloat16 l1 = __float2bfloat16_rn(v.y - __bfloat162float(h1));
    __nv_bfloat16 l2 = __float2bfloat16_rn(v.z - __bfloat162float(h2));
    __nv_bfloat16 l3 = __float2bfloat16_rn(v.w - __bfloat162float(h3));
    __nv_bfloat162 hp0(h0, h1), hp1(h2, h3), lp0(l0, l1), lp1(l2, l3);
    uint2 hv, lv;
    hv.x = *(uint32_t*)&hp0; hv.y = *(uint32_t*)&hp1;
    lv.x = *(uint32_t*)&lp0; lv.y = *(uint32_t*)&lp1;
    ((uint2*)hi)[i4] = hv;
    ((uint2*)lo)[i4] = lv;
}

__global__ void __launch_bounds__(256) conv_wT(const float* __restrict__ W,
                                               __nv_bfloat16* __restrict__ Thi,
                                               __nv_bfloat16* __restrict__ Tlo,
                                               int N)
{
    __shared__ float s[32][33];
    const int tx = threadIdx.x, ty = threadIdx.y;
    const int kt = blockIdx.y * 32, nt = blockIdx.x * 32;
#pragma unroll
    for (int r = 0; r < 4; r++) {
        int k = ty + r * 8;
        s[k][tx] = W[(size_t)(kt + k) * N + nt + tx];
    }
    __syncthreads();
#pragma unroll
    for (int r = 0; r < 4; r++) {
        int n = ty + r * 8;
        float v = s[tx][n];
        __nv_bfloat16 h = __float2bfloat16_rn(v);
        __nv_bfloat16 l = __float2bfloat16_rn(v - __bfloat162float(h));
        size_t o = (size_t)(nt + n) * 1024 + kt + tx;
        Thi[o] = h; Tlo[o] = l;
    }
}

// ---------------------------------------------------------------------------
// HMMA split-bf16 GEMM. Output either fp32 (+bias) or bf16 hi/lo (*oscale).
// ---------------------------------------------------------------------------
#define TILE_B   18432
#define BUF_B    (4 * TILE_B)
#define GEMM_SMEM (2 * BUF_B)

__global__ void __launch_bounds__(256) gemm_hmma(const __nv_bfloat16* __restrict__ Ahi,
                                                 const __nv_bfloat16* __restrict__ Alo,
                                                 const __nv_bfloat16* __restrict__ Bhi,
                                                 const __nv_bfloat16* __restrict__ Blo,
                                                 float* __restrict__ C,
                                                 __nv_bfloat16* __restrict__ Chi,
                                                 __nv_bfloat16* __restrict__ Clo,
                                                 float oscale,
                                                 int N,
                                                 const float* __restrict__ bias)
{
    extern __shared__ char smem[];
    const uint32_t sbase = smem_u32(smem);
    const int t    = threadIdx.x;
    const int lane = t & 31;
    const int wid  = t >> 5;
    const int bm   = blockIdx.y * 128;
    const int bn   = blockIdx.x * 128;
    const int wm   = (wid >> 1) * 32;
    const int wn   = (wid & 1) * 64;

    const uint32_t a_off = (uint32_t)(wm + (lane & 15)) * 144 + (uint32_t)(lane >> 4) * 16;
    const uint32_t b_off = (uint32_t)(wn + ((lane >> 4) & 1) * 8 + (lane & 7)) * 144
                         + (uint32_t)((lane >> 3) & 1) * 16;

    const __nv_bfloat16* srcs[4] = { Ahi + (size_t)bm * 1024, Alo + (size_t)bm * 1024,
                                     Bhi + (size_t)bn * 1024, Blo + (size_t)bn * 1024 };

    auto issue = [&](int it) {
        const uint32_t bufb = sbase + (it & 1) * BUF_B;
        const int k0 = it * 64;
#pragma unroll
        for (int r = 0; r < 4; r++) {
            const __nv_bfloat16* gb = srcs[r] + k0;
            const uint32_t sb = bufb + r * TILE_B;
#pragma unroll
            for (int i = 0; i < 4; i++) {
                int c   = i * 256 + t;
                int row = c >> 3;
                int col = c & 7;
                CP_ASYNC16(sb + row * 144 + col * 16,
                           gb + (size_t)row * 1024 + col * 8);
            }
        }
        CP_COMMIT();
    };

    float c[2][8][4];
#pragma unroll
    for (int mi = 0; mi < 2; mi++)
#pragma unroll
        for (int nj = 0; nj < 8; nj++)
#pragma unroll
            for (int k = 0; k < 4; k++) c[mi][nj][k] = 0.f;

    issue(0);
    issue(1);

    const int NITER = 16;
    for (int it = 0; it < NITER; it++) {
        if (it + 1 < NITER) { CP_WAIT1(); } else { CP_WAIT0(); }
        __syncthreads();

        const uint32_t bufb = sbase + (it & 1) * BUF_B;
        const uint32_t Ah = bufb, Al = bufb + TILE_B, Bh = bufb + 2 * TILE_B, Bl = bufb + 3 * TILE_B;

#pragma unroll
        for (int ks = 0; ks < 4; ks++) {
            const uint32_t ko = ks * 32;
            uint32_t ah0[4], ah1[4], al0[4], al1[4];
            ldsm4(ah0, Ah + a_off + ko);
            ldsm4(ah1, Ah + a_off + 16 * 144 + ko);
            ldsm4(al0, Al + a_off + ko);
            ldsm4(al1, Al + a_off + 16 * 144 + ko);
            uint32_t bh[4][4], bl[4][4];
#pragma unroll
            for (int jj = 0; jj < 4; jj++) {
                ldsm4(bh[jj], Bh + b_off + jj * 16 * 144 + ko);
                ldsm4(bl[jj], Bl + b_off + jj * 16 * 144 + ko);
            }
#pragma unroll
            for (int nj = 0; nj < 8; nj++) {
                const uint32_t bh0 = bh[nj >> 1][(nj & 1) * 2], bh1 = bh[nj >> 1][(nj & 1) * 2 + 1];
                const uint32_t bl0 = bl[nj >> 1][(nj & 1) * 2], bl1 = bl[nj >> 1][(nj & 1) * 2 + 1];
                mma16816(c[0][nj], ah0, bh0, bh1);
                mma16816(c[1][nj], ah1, bh0, bh1);
                mma16816(c[0][nj], al0, bh0, bh1);
                mma16816(c[1][nj], al1, bh0, bh1);
                mma16816(c[0][nj], ah0, bl0, bl1);
                mma16816(c[1][nj], ah1, bl0, bl1);
            }
        }
        __syncthreads();
        if (it + 2 < NITER) issue(it + 2);
    }

    const int g = lane >> 2, tg = lane & 3;
#pragma unroll
    for (int mi = 0; mi < 2; mi++) {
#pragma unroll
        for (int nj = 0; nj < 8; nj++) {
            int row = bm + wm + 16 * mi + g;
            int col = bn + wn + 8 * nj + 2 * tg;
            if (Chi) {
                float v0 = c[mi][nj][0] * oscale, v1 = c[mi][nj][1] * oscale;
                float v2 = c[mi][nj][2] * oscale, v3 = c[mi][nj][3] * oscale;
                __nv_bfloat16 h0 = __float2bfloat16_rn(v0), h1 = __float2bfloat16_rn(v1);
                __nv_bfloat16 h2 = __float2bfloat16_rn(v2), h3 = __float2bfloat16_rn(v3);
                __nv_bfloat162 hp0(h0, h1), hp1(h2, h3);
                __nv_bfloat162 lp0(__float2bfloat16_rn(v0 - __bfloat162float(h0)),
                                   __float2bfloat16_rn(v1 - __bfloat162float(h1)));
                __nv_bfloat162 lp1(__float2bfloat16_rn(v2 - __bfloat162float(h2)),
                                   __float2bfloat16_rn(v3 - __bfloat162float(h3)));
                *(uint32_t*)(Chi + (size_t)row * N + col)       = *(uint32_t*)&hp0;
                *(uint32_t*)(Clo + (size_t)row * N + col)       = *(uint32_t*)&lp0;
                *(uint32_t*)(Chi + (size_t)(row + 8) * N + col) = *(uint32_t*)&hp1;
                *(uint32_t*)(Clo + (size_t)(row + 8) * N + col) = *(uint32_t*)&lp1;
            } else {
                float b0 = 0.f, b1 = 0.f;
                if (bias) { b0 = bias[col]; b1 = bias[col + 1]; }
                float2 v0 = make_float2(c[mi][nj][0] + b0, c[mi][nj][1] + b1);
                float2 v1 = make_float2(c[mi][nj][2] + b0, c[mi][nj][3] + b1);
                *(float2*)(C + (size_t)row * N + col)       = v0;
                *(float2*)(C + (size_t)(row + 8) * N + col) = v1;
            }
        }
    }
}

// ---------------------------------------------------------------------------
// HMMA causal flash attention. Block = 128 q rows x 1 head. 8 warps (m16 each).
// kv tiles of 64 keys, double-buffered cp.async. S and P via 3-term bf16 split.
// q pre-scaled by SCALE*log2(e) -> softmax in exp2 domain.
// smem: Khi|Klo|Vhi|Vlo per buffer, rows padded to 144B. 2*36864 = 73728 B.
// ---------------------------------------------------------------------------
#define KT_B   9216            // 64 rows * 144 B
#define ABUF_B (4 * KT_B)      // 36864
#define ATTN_SMEM (2 * ABUF_B) // 73728

__global__ void __launch_bounds__(256) attn_mma(const __nv_bfloat16* __restrict__ Qhi,
                                                const __nv_bfloat16* __restrict__ Qlo,
                                                const __nv_bfloat16* __restrict__ KVhi,
                                                const __nv_bfloat16* __restrict__ KVlo,
                                                __nv_bfloat16* __restrict__ Ohi,
                                                __nv_bfloat16* __restrict__ Olo)
{
    extern __shared__ char smem[];
    const uint32_t sbase = smem_u32(smem);
    const int t    = threadIdx.x;
    const int lane = t & 31;
    const int wid  = t >> 5;
    const int g    = lane >> 2;
    const int tg   = lane & 3;

    const int qt = 15 - (int)blockIdx.x;     // heavy tiles first
    const int h  = blockIdx.y;
    const int b  = blockIdx.z;
    const int qb = qt * 128;
    const int wm = wid * 16;

    // -------- stage Q tile (128 x 64 hi/lo) into smem, load A frags --------
    {
        const __nv_bfloat16* qh_g = Qhi + ((size_t)(b * 2048 + qb)) * 1024 + h * 64;
        const __nv_bfloat16* ql_g = Qlo + ((size_t)(b * 2048 + qb)) * 1024 + h * 64;
#pragma unroll
        for (int i = 0; i < 4; i++) {
            int idx = i * 256 + t;           // 0..1023
            int row = idx >> 3, cc = idx & 7;
            CP_ASYNC16(sbase + row * 144 + cc * 16, qh_g + (size_t)row * 1024 + cc * 8);
            CP_ASYNC16(sbase + 18432 + row * 144 + cc * 16, ql_g + (size_t)row * 1024 + cc * 8);
        }
        CP_COMMIT();
        CP_WAIT0();
        __syncthreads();
    }
    uint32_t qh[4][4], ql[4][4];
    {
        const uint32_t a_base = (uint32_t)(wm + (lane & 15)) * 144 + (uint32_t)(lane >> 4) * 16;
#pragma unroll
        for (int ks = 0; ks < 4; ks++) {
            ldsm4(qh[ks], sbase + a_base + ks * 32);
            ldsm4(ql[ks], sbase + 18432 + a_base + ks * 32);
        }
    }
    __syncthreads();   // Q frags in regs before buffers get overwritten

    // -------- kv pipeline --------
    const __nv_bfloat16* kv_h = KVhi + ((size_t)(b * 2048)) * 2048 + h * 64;
    const __nv_bfloat16* kv_l = KVlo + ((size_t)(b * 2048)) * 2048 + h * 64;
    const int ntk = 2 * (qt + 1);

    auto issue = [&](int kt) {
        const uint32_t bufb = sbase + (kt & 1) * ABUF_B;
        const size_t rbase = (size_t)(kt * 64) * 2048;
        const __nv_bfloat16* srcs[4] = { kv_h + rbase, kv_l + rbase,
                                         kv_h + rbase + 1024, kv_l + rbase + 1024 };
#pragma unroll
        for (int r = 0; r < 4; r++) {
#pragma unroll
            for (int i = 0; i < 2; i++) {
                int idx = i * 256 + t;       // 0..511
                int row = idx >> 3, cc = idx & 7;
                CP_ASYNC16(bufb + r * KT_B + row * 144 + cc * 16,
                           srcs[r] + (size_t)row * 2048 + cc * 8);
            }
        }
        CP_COMMIT();
    };

    issue(0);
    issue(1);

    // per-thread softmax state (rows g and g+8 of warp tile)
    float m0 = -1e30f, m1 = -1e30f, l0 = 0.f, l1 = 0.f;
    float o[8][4];
#pragma unroll
    for (int nj = 0; nj < 8; nj++)
#pragma unroll
        for (int k = 0; k < 4; k++) o[nj][k] = 0.f;

    const uint32_t b_off = (uint32_t)(((lane >> 4) & 1) * 8 + (lane & 7)) * 144
                         + (uint32_t)((lane >> 3) & 1) * 16;
    const uint32_t v_off = (uint32_t)((lane & 7) + ((lane >> 3) & 1) * 8) * 144
                         + (uint32_t)(lane >> 4) * 16;

    for (int kt = 0; kt < ntk; kt++) {
        if (kt + 1 < ntk) { CP_WAIT1(); } else { CP_WAIT0(); }
        __syncthreads();

        const uint32_t bufb = sbase + (kt & 1) * ABUF_B;
        const uint32_t Kh = bufb, Kl = bufb + KT_B, Vh = bufb + 2 * KT_B, Vl = bufb + 3 * KT_B;
        const int kb = kt * 64;

        // ---- S = Q K^T ----
        float s[8][4];
#pragma unroll
        for (int nj = 0; nj < 8; nj++)
#pragma unroll
            for (int k = 0; k < 4; k++) s[nj][k] = 0.f;

#pragma unroll
        for (int ks = 0; ks < 4; ks++) {
            const uint32_t ko = ks * 32;
#pragma unroll
            for (int nj2 = 0; nj2 < 4; nj2++) {
                uint32_t kh[4], kl[4];
                ldsm4(kh, Kh + b_off + nj2 * 16 * 144 + ko);
                ldsm4(kl, Kl + b_off + nj2 * 16 * 144 + ko);
                mma16816(s[2 * nj2],     qh[ks], kh[0], kh[1]);
                mma16816(s[2 * nj2],     ql[ks], kh[0], kh[1]);
                mma16816(s[2 * nj2],     qh[ks], kl[0], kl[1]);
                mma16816(s[2 * nj2 + 1], qh[ks], kh[2], kh[3]);
                mma16816(s[2 * nj2 + 1], ql[ks], kh[2], kh[3]);
                mma16816(s[2 * nj2 + 1], qh[ks], kl[2], kl[3]);
            }
        }

        // ---- causal mask (only when tile may cross the diagonal) ----
        const int row0 = qb + wm + g, row1 = row0 + 8;
        if (kb + 63 > qb + wm) {
#pragma unroll
            for (int nj = 0; nj < 8; nj++) {
                int col = kb + 8 * nj + 2 * tg;
                if (col     > row0) s[nj][0] = -1e30f;
                if (col + 1 > row0) s[nj][1] = -1e30f;
                if (col     > row1) s[nj][2] = -1e30f;
                if (col + 1 > row1) s[nj][3] = -1e30f;
            }
        }

        // ---- online softmax ----
        float tm0 = -1e30f, tm1 = -1e30f;
#pragma unroll
        for (int nj = 0; nj < 8; nj++) {
            tm0 = fmaxf(tm0, fmaxf(s[nj][0], s[nj][1]));
            tm1 = fmaxf(tm1, fmaxf(s[nj][2], s[nj][3]));
        }
        tm0 = fmaxf(tm0, __shfl_xor_sync(0xffffffffu, tm0, 1));
        tm0 = fmaxf(tm0, __shfl_xor_sync(0xffffffffu, tm0, 2));
        tm1 = fmaxf(tm1, __shfl_xor_sync(0xffffffffu, tm1, 1));
        tm1 = fmaxf(tm1, __shfl_xor_sync(0xffffffffu, tm1, 2));

        float mn0 = fmaxf(m0, tm0), mn1 = fmaxf(m1, tm1);
        float a0 = fast_exp2(m0 - mn0), a1 = fast_exp2(m1 - mn1);
        m0 = mn0; m1 = mn1;

        float sum0 = 0.f, sum1 = 0.f;
#pragma unroll
        for (int nj = 0; nj < 8; nj++) {
            s[nj][0] = fast_exp2(s[nj][0] - mn0);
            s[nj][1] = fast_exp2(s[nj][1] - mn0);
            s[nj][2] = fast_exp2(s[nj][2] - mn1);
            s[nj][3] = fast_exp2(s[nj][3] - mn1);
            sum0 += s[nj][0] + s[nj][1];
            sum1 += s[nj][2] + s[nj][3];
        }
        sum0 += __shfl_xor_sync(0xffffffffu, sum0, 1);
        sum0 += __shfl_xor_sync(0xffffffffu, sum0, 2);
        sum1 += __shfl_xor_sync(0xffffffffu, sum1, 1);
        sum1 += __shfl_xor_sync(0xffffffffu, sum1, 2);
        l0 = l0 * a0 + sum0;
        l1 = l1 * a1 + sum1;

#pragma unroll
        for (int nj = 0; nj < 8; nj++) {
            o[nj][0] *= a0; o[nj][1] *= a0;
            o[nj][2] *= a1; o[nj][3] *= a1;
        }

        // ---- O += P V ----
#pragma unroll
        for (int ks = 0; ks < 4; ks++) {
            uint32_t phi[4], plo[4];
            {
                float p00 = s[2 * ks][0], p01 = s[2 * ks][1];
                float p02 = s[2 * ks][2], p03 = s[2 * ks][3];
                float p10 = s[2 * ks + 1][0], p11 = s[2 * ks + 1][1];
                float p12 = s[2 * ks + 1][2], p13 = s[2 * ks + 1][3];
                phi[0] = pack_bf16(p00, p01);
                phi[1] = pack_bf16(p02, p03);
                phi[2] = pack_bf16(p10, p11);
                phi[3] = pack_bf16(p12, p13);
                plo[0] = pack_bf16(p00 - __bfloat162float(__float2bfloat16_rn(p00)),
                                   p01 - __bfloat162float(__float2bfloat16_rn(p01)));
                plo[1] = pack_bf16(p02 - __bfloat162float(__float2bfloat16_rn(p02)),
                                   p03 - __bfloat162float(__float2bfloat16_rn(p03)));
                plo[2] = pack_bf16(p10 - __bfloat162float(__float2bfloat16_rn(p10)),
                                   p11 - __bfloat162float(__float2bfloat16_rn(p11)));
                plo[3] = pack_bf16(p12 - __bfloat162float(__float2bfloat16_rn(p12)),
                                   p13 - __bfloat162float(__float2bfloat16_rn(p13)));
            }
            const uint32_t kro = ks * 16 * 144;
#pragma unroll
            for (int dc = 0; dc < 4; dc++) {
                uint32_t vh[4], vl[4];
                ldsm4t(vh, Vh + v_off + kro + dc * 32);
                ldsm4t(vl, Vl + v_off + kro + dc * 32);
                mma16816(o[2 * dc],     phi, vh[0], vh[1]);
                mma16816(o[2 * dc],     plo, vh[0], vh[1]);
                mma16816(o[2 * dc],     phi, vl[0], vl[1]);
                mma16816(o[2 * dc + 1], phi, vh[2], vh[3]);
                mma16816(o[2 * dc + 1], plo, vh[2], vh[3]);
                mma16816(o[2 * dc + 1], phi, vl[2], vl[3]);
            }
        }

        __syncthreads();
        if (kt + 2 < ntk) issue(kt + 2);
    }

    // ---- epilogue: O / l -> bf16 hi/lo ----
    const float inv0 = 1.0f / l0, inv1 = 1.0f / l1;
    const int row0 = b * 2048 + qb + wm + g;
#pragma unroll
    for (int nj = 0; nj < 8; nj++) {
        int col = h * 64 + 8 * nj + 2 * tg;
        float v0 = o[nj][0] * inv0, v1 = o[nj][1] * inv0;
        float v2 = o[nj][2] * inv1, v3 = o[nj][3] * inv1;
        __nv_bfloat16 h0 = __float2bfloat16_rn(v0), h1 = __float2bfloat16_rn(v1);
        __nv_bfloat16 h2 = __float2bfloat16_rn(v2), h3 = __float2bfloat16_rn(v3);
        __nv_bfloat162 hp0(h0, h1), hp1(h2, h3);
        __nv_bfloat162 lp0(__float2bfloat16_rn(v0 - __bfloat162float(h0)),
                           __float2bfloat16_rn(v1 - __bfloat162float(h1)));
        __nv_bfloat162 lp1(__float2bfloat16_rn(v2 - __bfloat162float(h2)),
                           __float2bfloat16_rn(v3 - __bfloat162float(h3)));
        *(uint32_t*)(Ohi + (size_t)row0 * 1024 + col)       = *(uint32_t*)&hp0;
        *(uint32_t*)(Olo + (size_t)row0 * 1024 + col)       = *(uint32_t*)&lp0;
        *(uint32_t*)(Ohi + (size_t)(row0 + 8) * 1024 + col) = *(uint32_t*)&hp1;
        *(uint32_t*)(Olo + (size_t)(row0 + 8) * 1024 + col) = *(uint32_t*)&lp1;
    }
}

// ---------------------------------------------------------------------------
// Launch
// ---------------------------------------------------------------------------
extern "C" void kernel_launch(void* const* d_in, const int* in_sizes, int n_in,
                              void* d_out, int out_size)
{
    (void)in_sizes; (void)n_in; (void)out_size;
    const float* x   = (const float*)d_in[0];
    const float* Wq  = (const float*)d_in[1];
    const float* Wkv = (const float*)d_in[2];
    const float* Wo  = (const float*)d_in[3];
    const float* bo  = (const float*)d_in[4];
    float* out = (float*)d_out;

    __nv_bfloat16 *xhi, *xlo, *wthi, *wtlo, *qhi, *qlo, *kvhi, *kvlo, *ohi, *olo;
    cudaGetSymbolAddress((void**)&xhi,  g_xhi);
    cudaGetSymbolAddress((void**)&xlo,  g_xlo);
    cudaGetSymbolAddress((void**)&wthi, g_wthi);
    cudaGetSymbolAddress((void**)&wtlo, g_wtlo);
    cudaGetSymbolAddress((void**)&qhi,  g_qhi);
    cudaGetSymbolAddress((void**)&qlo,  g_qlo);
    cudaGetSymbolAddress((void**)&kvhi, g_kvhi);
    cudaGetSymbolAddress((void**)&kvlo, g_kvlo);
    cudaGetSymbolAddress((void**)&ohi,  g_ohi);
    cudaGetSymbolAddress((void**)&olo,  g_olo);

    cudaFuncSetAttribute(gemm_hmma, cudaFuncAttributeMaxDynamicSharedMemorySize, GEMM_SMEM);
    cudaFuncSetAttribute(attn_mma,  cudaFuncAttributeMaxDynamicSharedMemorySize, ATTN_SMEM);

    __nv_bfloat16 *wq_hi = wthi,            *wq_lo = wtlo;
    __nv_bfloat16 *wkv_hi = wthi + 1048576, *wkv_lo = wtlo + 1048576;
    __nv_bfloat16 *wo_hi = wthi + 3145728,  *wo_lo = wtlo + 3145728;

    const float qscale = 0.125f * 1.4426950408889634f;   // D^-0.5 * log2(e)

    conv_split<<<8192, 256>>>(x, xhi, xlo);
    conv_wT<<<dim3(32, 32), dim3(32, 8)>>>(Wq,  wq_hi,  wq_lo,  1024);
    conv_wT<<<dim3(64, 32), dim3(32, 8)>>>(Wkv, wkv_hi, wkv_lo, 2048);
    conv_wT<<<dim3(32, 32), dim3(32, 8)>>>(Wo,  wo_hi,  wo_lo,  1024);

    // q = (x @ Wq) * qscale   -> bf16 hi/lo
    gemm_hmma<<<dim3(8,  64), 256, GEMM_SMEM>>>(xhi, xlo, wq_hi,  wq_lo,
                                                nullptr, qhi, qlo, qscale, 1024, nullptr);
    // kv = x @ Wkv            -> bf16 hi/lo
    gemm_hmma<<<dim3(16, 64), 256, GEMM_SMEM>>>(xhi, xlo, wkv_hi, wkv_lo,
                                                nullptr, kvhi, kvlo, 1.0f, 2048, nullptr);
    // attention -> bf16 hi/lo
    attn_mma<<<dim3(16, 16, 4), 256, ATTN_SMEM>>>(qhi, qlo, kvhi, kvlo, ohi, olo);
    // out = o @ Wo + bo       -> fp32
    gemm_hmma<<<dim3(8, 64), 256, GEMM_SMEM>>>(ohi, olo, wo_hi, wo_lo,
                                               out, nullptr, nullptr, 1.0f, 1024, bo);
}